// round 5
// baseline (speedup 1.0000x reference)
#include <cuda_runtime.h>
#include <cstring>

#define NBATCH 256
#define NN     64
#define DT     4096
#define NPAIR  2048
#define THREADS 256

__device__ float e_scratch[NBATCH * NN];   // row variances (K1a -> K1b)

__device__ __forceinline__ void fma2(unsigned long long &d,
                                     unsigned long long a,
                                     unsigned long long b) {
    asm("fma.rn.f32x2 %0, %1, %2, %0;" : "+l"(d) : "l"(a), "l"(b));
}

// ============================================================================
// K1a: row variances (ddof=1). 1024 blocks = (batch, 16-row group).
// ============================================================================
__global__ void __launch_bounds__(THREADS)
dga_var(const float* __restrict__ x)
{
    const int b    = blockIdx.x >> 2;
    const int g    = blockIdx.x & 3;
    const int tid  = threadIdx.x;
    const int warp = tid >> 5;
    const int lane = tid & 31;
    const float* xb = x + (size_t)b * NN * DT;

    #pragma unroll
    for (int rr = 0; rr < 2; ++rr) {
        const int r = g * 16 + warp * 2 + rr;
        const float4* row = (const float4*)(xb + (size_t)r * DT);
        float s = 0.f, ss = 0.f;
        #pragma unroll
        for (int k = 0; k < 32; ++k) {
            float4 v = row[lane + 32 * k];
            s  += (v.x + v.y) + (v.z + v.w);
            ss += v.x * v.x + v.y * v.y + v.z * v.z + v.w * v.w;
        }
        #pragma unroll
        for (int m = 16; m; m >>= 1) {
            s  += __shfl_xor_sync(0xffffffffu, s,  m);
            ss += __shfl_xor_sync(0xffffffffu, ss, m);
        }
        if (lane == 0) {
            float mean = s * (1.0f / DT);
            e_scratch[b * NN + r] = (ss - s * mean) * (1.0f / (DT - 1));
        }
    }
}

// ============================================================================
// K1b: 4 scalar coefs -> masked softmax -> attn_weights. 256 blocks.
// ============================================================================
__global__ void __launch_bounds__(THREADS)
dga_weights(const float* __restrict__ wq, const float* __restrict__ bq,
            const float* __restrict__ wk, const float* __restrict__ bk,
            float* __restrict__ attn)
{
    __shared__ float e_sm[NN];
    __shared__ float coef[4];

    const int b   = blockIdx.x;
    const int tid = threadIdx.x;

    if (tid < NN) e_sm[tid] = e_scratch[b * NN + tid];
    if (tid == 0) {
        float A = 0.f, B = 0.f, C = 0.f, Dc = 0.f;
        #pragma unroll
        for (int h = 0; h < 16; ++h) {
            float q = wq[h], qb = bq[h], k = wk[h], kb = bk[h];
            A += q * k; B += q * kb; C += qb * k; Dc += qb * kb;
        }
        coef[0] = A; coef[1] = B; coef[2] = C; coef[3] = Dc;
    }
    __syncthreads();

    const int i  = tid >> 2;
    const int jg = tid & 3;
    const float ei = e_sm[i];
    const float m1 = 0.25f * (coef[0] * ei + coef[2]);   // SCALE = 0.25
    const float m0 = 0.25f * (coef[1] * ei + coef[3]);
    float sv[16];
    float mx = -3.4e38f;
    #pragma unroll
    for (int t = 0; t < 16; ++t) {
        int j = jg * 16 + t;
        float s = fmaf(m1, e_sm[j], m0);
        if (j == i) s = -1000000000.0f;
        sv[t] = s;
        mx = fmaxf(mx, s);
    }
    #pragma unroll
    for (int m = 1; m < 4; m <<= 1)
        mx = fmaxf(mx, __shfl_xor_sync(0xffffffffu, mx, m));
    float sum = 0.f;
    #pragma unroll
    for (int t = 0; t < 16; ++t) { sv[t] = __expf(sv[t] - mx); sum += sv[t]; }
    #pragma unroll
    for (int m = 1; m < 4; m <<= 1)
        sum += __shfl_xor_sync(0xffffffffu, sum, m);
    float inv = 1.0f / sum;

    float* arow = attn + (((size_t)b * NN) + i) * NN;
    #pragma unroll
    for (int t = 0; t < 16; ++t)
        arow[jg * 16 + t] = sv[t] * inv;
}

// ============================================================================
// K2: out[b,i,t] = x[b,i,t] + sum_j attn[b,i,j] * x[b,j,t]
// 2048 blocks = (batch, eighth of pairs). Per chunk of 128 pairs: stage x
// slab to smem; each thread computes 16 rows x 2 pairs (f32x2).
// Per k-step per warp: 1 v-LDS.128 + 4 bcast w-LDS.128 -> 32 FFMA2.
// ============================================================================
#define WROW_PAD 66
#define SMEM_W_BYTES (NN * WROW_PAD * 8)               // 33792
#define SMEM_TOTAL   (SMEM_W_BYTES + NN * 128 * 8)     // 99328

__global__ void __launch_bounds__(THREADS)
dga_gemm(const float* __restrict__ x, const float* __restrict__ attn,
         float* __restrict__ out)
{
    extern __shared__ char smem_raw[];
    float2 (*wdupT)[WROW_PAD] = (float2 (*)[WROW_PAD])smem_raw;  // [j][i] (w,w)
    float2 (*vs)[128]         = (float2 (*)[128])(smem_raw + SMEM_W_BYTES);

    const int bx   = blockIdx.x;
    const int b    = bx >> 3;
    const int o    = bx & 7;
    const int tid  = threadIdx.x;
    const int warp = tid >> 5;
    const int lane = tid & 31;

    const float* xb = x    + (size_t)b * NN * DT;
    const float* ab = attn + (size_t)b * NN * NN;
    float*       ob = out  + (size_t)b * NN * DT;

    // stage weights transposed + duplicated: attn[i][j] -> wdupT[j][i]=(w,w)
    #pragma unroll
    for (int t = 0; t < 16; ++t) {
        int idx = tid + 256 * t;
        int i = idx >> 6, j = idx & 63;
        float w = ab[idx];
        wdupT[j][i] = make_float2(w, w);
    }

    const int i0 = (warp >> 1) * 16;            // 16 output rows per warp
    const int pl = (warp & 1) * 64 + 2 * lane;  // local pair idx (float2 units)

    #pragma unroll 1
    for (int c = 0; c < 2; ++c) {
        const int pbase = o * 256 + c * 128;
        __syncthreads();                         // vs free from previous chunk

        // stage vs[j][0..127] <- x[j][pbase..pbase+128) pairs (4096 float4)
        #pragma unroll
        for (int t = 0; t < 16; ++t) {
            int u  = tid + 256 * t;
            int j  = u >> 6;
            int f4 = u & 63;
            float4 vv = *(const float4*)(xb + (size_t)j * DT + 2 * pbase + f4 * 4);
            *(float4*)&vs[j][f4 * 2] = vv;
        }
        __syncthreads();

        // accumulators init = residual x
        unsigned long long acc[16][2];
        #pragma unroll
        for (int r = 0; r < 16; ++r) {
            ulonglong2 t2 = *(const ulonglong2*)&vs[i0 + r][pl];
            acc[r][0] = t2.x; acc[r][1] = t2.y;
        }

        #pragma unroll 2
        for (int k = 0; k < NN; ++k) {
            ulonglong2 v = *(const ulonglong2*)&vs[k][pl];
            #pragma unroll
            for (int rr = 0; rr < 16; rr += 4) {
                ulonglong2 w01 = *(const ulonglong2*)&wdupT[k][i0 + rr];
                ulonglong2 w23 = *(const ulonglong2*)&wdupT[k][i0 + rr + 2];
                fma2(acc[rr    ][0], w01.x, v.x);
                fma2(acc[rr    ][1], w01.x, v.y);
                fma2(acc[rr + 1][0], w01.y, v.x);
                fma2(acc[rr + 1][1], w01.y, v.y);
                fma2(acc[rr + 2][0], w23.x, v.x);
                fma2(acc[rr + 2][1], w23.x, v.y);
                fma2(acc[rr + 3][0], w23.y, v.x);
                fma2(acc[rr + 3][1], w23.y, v.y);
            }
        }

        // store (coalesced 16B per lane)
        #pragma unroll
        for (int r = 0; r < 16; ++r) {
            unsigned long long* orow =
                (unsigned long long*)(ob + (size_t)(i0 + r) * DT) + pbase;
            ulonglong2 t2; t2.x = acc[r][0]; t2.y = acc[r][1];
            *(ulonglong2*)&orow[pl] = t2;
        }
    }
}

extern "C" void kernel_launch(void* const* d_in, const int* in_sizes, int n_in,
                              void* d_out, int out_size) {
    const float* x  = (const float*)d_in[0];
    const float* wq = (const float*)d_in[1];
    const float* bq = (const float*)d_in[2];
    const float* wk = (const float*)d_in[3];
    const float* bk = (const float*)d_in[4];
    float* out  = (float*)d_out;
    float* attn = out + (size_t)NBATCH * NN * DT;   // out tensor first, then attn

    cudaFuncSetAttribute(dga_gemm, cudaFuncAttributeMaxDynamicSharedMemorySize,
                         SMEM_TOTAL);

    dga_var<<<NBATCH * 4, THREADS>>>(x);
    dga_weights<<<NBATCH, THREADS>>>(wq, bq, wk, bk, attn);
    dga_gemm<<<NBATCH * 8, THREADS, SMEM_TOTAL>>>(x, attn, out);
}

// round 6
// speedup vs baseline: 1.2612x; 1.2612x over previous
#include <cuda_runtime.h>
#include <cstring>

#define NBATCH 256
#define NN     64
#define DT     4096
#define THREADS 256

__device__ float e_scratch[NBATCH * NN];   // row variances (K1a -> K1b)

__device__ __forceinline__ void fma2(unsigned long long &d,
                                     unsigned long long a,
                                     unsigned long long b) {
    asm("fma.rn.f32x2 %0, %1, %2, %0;" : "+l"(d) : "l"(a), "l"(b));
}
__device__ __forceinline__ unsigned long long dup2(float w) {
    unsigned long long r;
    asm("mov.b64 %0, {%1, %1};" : "=l"(r) : "f"(w));
    return r;
}
__device__ __forceinline__ void cp_async16(void* smem_dst, const void* gsrc) {
    unsigned sa = (unsigned)__cvta_generic_to_shared(smem_dst);
    asm volatile("cp.async.cg.shared.global [%0], [%1], 16;" :: "r"(sa), "l"(gsrc));
}

// ============================================================================
// K1a: row variances (ddof=1). 1024 blocks = (batch, 16-row group).
// ============================================================================
__global__ void __launch_bounds__(THREADS)
dga_var(const float* __restrict__ x)
{
    const int b    = blockIdx.x >> 2;
    const int g    = blockIdx.x & 3;
    const int tid  = threadIdx.x;
    const int warp = tid >> 5;
    const int lane = tid & 31;
    const float* xb = x + (size_t)b * NN * DT;

    #pragma unroll
    for (int rr = 0; rr < 2; ++rr) {
        const int r = g * 16 + warp * 2 + rr;
        const float4* row = (const float4*)(xb + (size_t)r * DT);
        float s = 0.f, ss = 0.f;
        #pragma unroll
        for (int k = 0; k < 32; ++k) {
            float4 v = row[lane + 32 * k];
            s  += (v.x + v.y) + (v.z + v.w);
            ss += v.x * v.x + v.y * v.y + v.z * v.z + v.w * v.w;
        }
        #pragma unroll
        for (int m = 16; m; m >>= 1) {
            s  += __shfl_xor_sync(0xffffffffu, s,  m);
            ss += __shfl_xor_sync(0xffffffffu, ss, m);
        }
        if (lane == 0) {
            float mean = s * (1.0f / DT);
            e_scratch[b * NN + r] = (ss - s * mean) * (1.0f / (DT - 1));
        }
    }
}

// ============================================================================
// K1b: 4 scalar coefs -> masked softmax -> attn_weights. 256 blocks.
// ============================================================================
__global__ void __launch_bounds__(THREADS)
dga_weights(const float* __restrict__ wq, const float* __restrict__ bq,
            const float* __restrict__ wk, const float* __restrict__ bk,
            float* __restrict__ attn)
{
    __shared__ float e_sm[NN];
    __shared__ float coef[4];

    const int b   = blockIdx.x;
    const int tid = threadIdx.x;

    if (tid < NN) e_sm[tid] = e_scratch[b * NN + tid];
    if (tid == 0) {
        float A = 0.f, B = 0.f, C = 0.f, Dc = 0.f;
        #pragma unroll
        for (int h = 0; h < 16; ++h) {
            float q = wq[h], qb = bq[h], k = wk[h], kb = bk[h];
            A += q * k; B += q * kb; C += qb * k; Dc += qb * kb;
        }
        coef[0] = A; coef[1] = B; coef[2] = C; coef[3] = Dc;
    }
    __syncthreads();

    const int i  = tid >> 2;
    const int jg = tid & 3;
    const float ei = e_sm[i];
    const float m1 = 0.25f * (coef[0] * ei + coef[2]);   // SCALE = 0.25
    const float m0 = 0.25f * (coef[1] * ei + coef[3]);
    float sv[16];
    float mx = -3.4e38f;
    #pragma unroll
    for (int t = 0; t < 16; ++t) {
        int j = jg * 16 + t;
        float s = fmaf(m1, e_sm[j], m0);
        if (j == i) s = -1000000000.0f;
        sv[t] = s;
        mx = fmaxf(mx, s);
    }
    #pragma unroll
    for (int m = 1; m < 4; m <<= 1)
        mx = fmaxf(mx, __shfl_xor_sync(0xffffffffu, mx, m));
    float sum = 0.f;
    #pragma unroll
    for (int t = 0; t < 16; ++t) { sv[t] = __expf(sv[t] - mx); sum += sv[t]; }
    #pragma unroll
    for (int m = 1; m < 4; m <<= 1)
        sum += __shfl_xor_sync(0xffffffffu, sum, m);
    float inv = 1.0f / sum;

    float* arow = attn + (((size_t)b * NN) + i) * NN;
    #pragma unroll
    for (int t = 0; t < 16; ++t)
        arow[jg * 16 + t] = sv[t] * inv;
}

// ============================================================================
// K2: out[b,i,t] = x[b,i,t] + sum_j attn[b,i,j] * x[b,j,t]
// 1024 blocks = (batch, quarter). 4 chunks of 128 pairs. 2 blocks/SM.
// Per thread: 8 rows x 4 pairs. Weights stored non-duplicated (17 KB);
// (w,w) operands built in-register on the idle ALU pipe.
// Per k per warp: 2 v-LDS.128 + 2 bcast w-LDS.128 -> 32 FFMA2.
// ============================================================================
#define WPAD 68                                     // floats per wT row (272B)
#define SMEM_W_BYTES (NN * WPAD * 4)                // 17408
#define SMEM_TOTAL   (SMEM_W_BYTES + NN * 128 * 8) // + 65536 = 82944

__global__ void __launch_bounds__(THREADS, 2)
dga_gemm(const float* __restrict__ x, const float* __restrict__ attn,
         float* __restrict__ out)
{
    extern __shared__ char smem_raw[];
    float  (*wT)[WPAD] = (float (*)[WPAD])smem_raw;              // [j][i]
    float2 (*vs)[128]  = (float2 (*)[128])(smem_raw + SMEM_W_BYTES);

    const int bx   = blockIdx.x;
    const int b    = bx >> 2;
    const int q    = bx & 3;
    const int tid  = threadIdx.x;
    const int warp = tid >> 5;
    const int lane = tid & 31;

    const float* xb = x    + (size_t)b * NN * DT;
    const float* ab = attn + (size_t)b * NN * NN;
    float*       ob = out  + (size_t)b * NN * DT;

    // stage weights transposed (non-dup): attn[i][j] -> wT[j][i]
    #pragma unroll
    for (int t = 0; t < 16; ++t) {
        int idx = tid + 256 * t;          // coalesced gmem read
        int i = idx >> 6, j = idx & 63;
        wT[j][i] = ab[idx];
    }

    const int i0 = warp * 8;              // this warp's 8 output rows

    #pragma unroll 1
    for (int c = 0; c < 4; ++c) {
        const int pbase = q * 512 + c * 128;   // pair base of this chunk
        __syncthreads();                       // vs free from previous chunk

        // stage vs[j][0..127] via cp.async (4096 x 16B)
        #pragma unroll
        for (int t = 0; t < 16; ++t) {
            int u  = tid + 256 * t;
            int j  = u >> 6;
            int f4 = u & 63;
            cp_async16(&vs[j][f4 * 2],
                       xb + (size_t)j * DT + 2 * pbase + f4 * 4);
        }
        asm volatile("cp.async.commit_group;");
        asm volatile("cp.async.wait_group 0;");
        __syncthreads();

        // accumulators init = residual x (folds the "+ x")
        unsigned long long acc[8][4];
        #pragma unroll
        for (int r = 0; r < 8; ++r) {
            ulonglong2 lo = *(const ulonglong2*)&vs[i0 + r][2 * lane];
            ulonglong2 hi = *(const ulonglong2*)&vs[i0 + r][64 + 2 * lane];
            acc[r][0] = lo.x; acc[r][1] = lo.y;
            acc[r][2] = hi.x; acc[r][3] = hi.y;
        }

        #pragma unroll 4
        for (int k = 0; k < NN; ++k) {
            ulonglong2 v01 = *(const ulonglong2*)&vs[k][2 * lane];
            ulonglong2 v23 = *(const ulonglong2*)&vs[k][64 + 2 * lane];
            float4 wa = *(const float4*)&wT[k][i0];      // bcast LDS.128
            float4 wb = *(const float4*)&wT[k][i0 + 4];  // bcast LDS.128
            unsigned long long w0 = dup2(wa.x), w1 = dup2(wa.y);
            unsigned long long w2 = dup2(wa.z), w3 = dup2(wa.w);
            unsigned long long w4 = dup2(wb.x), w5 = dup2(wb.y);
            unsigned long long w6 = dup2(wb.z), w7 = dup2(wb.w);
            fma2(acc[0][0], w0, v01.x); fma2(acc[0][1], w0, v01.y);
            fma2(acc[0][2], w0, v23.x); fma2(acc[0][3], w0, v23.y);
            fma2(acc[1][0], w1, v01.x); fma2(acc[1][1], w1, v01.y);
            fma2(acc[1][2], w1, v23.x); fma2(acc[1][3], w1, v23.y);
            fma2(acc[2][0], w2, v01.x); fma2(acc[2][1], w2, v01.y);
            fma2(acc[2][2], w2, v23.x); fma2(acc[2][3], w2, v23.y);
            fma2(acc[3][0], w3, v01.x); fma2(acc[3][1], w3, v01.y);
            fma2(acc[3][2], w3, v23.x); fma2(acc[3][3], w3, v23.y);
            fma2(acc[4][0], w4, v01.x); fma2(acc[4][1], w4, v01.y);
            fma2(acc[4][2], w4, v23.x); fma2(acc[4][3], w4, v23.y);
            fma2(acc[5][0], w5, v01.x); fma2(acc[5][1], w5, v01.y);
            fma2(acc[5][2], w5, v23.x); fma2(acc[5][3], w5, v23.y);
            fma2(acc[6][0], w6, v01.x); fma2(acc[6][1], w6, v01.y);
            fma2(acc[6][2], w6, v23.x); fma2(acc[6][3], w6, v23.y);
            fma2(acc[7][0], w7, v01.x); fma2(acc[7][1], w7, v01.y);
            fma2(acc[7][2], w7, v23.x); fma2(acc[7][3], w7, v23.y);
        }

        // store (coalesced STG.128)
        #pragma unroll
        for (int r = 0; r < 8; ++r) {
            unsigned long long* orow =
                (unsigned long long*)(ob + (size_t)(i0 + r) * DT) + pbase;
            ulonglong2 lo; lo.x = acc[r][0]; lo.y = acc[r][1];
            ulonglong2 hi; hi.x = acc[r][2]; hi.y = acc[r][3];
            *(ulonglong2*)&orow[2 * lane]      = lo;
            *(ulonglong2*)&orow[64 + 2 * lane] = hi;
        }
    }
}

extern "C" void kernel_launch(void* const* d_in, const int* in_sizes, int n_in,
                              void* d_out, int out_size) {
    const float* x  = (const float*)d_in[0];
    const float* wq = (const float*)d_in[1];
    const float* bq = (const float*)d_in[2];
    const float* wk = (const float*)d_in[3];
    const float* bk = (const float*)d_in[4];
    float* out  = (float*)d_out;
    float* attn = out + (size_t)NBATCH * NN * DT;   // out tensor first, then attn

    cudaFuncSetAttribute(dga_gemm, cudaFuncAttributeMaxDynamicSharedMemorySize,
                         SMEM_TOTAL);

    dga_var<<<NBATCH * 4, THREADS>>>(x);
    dga_weights<<<NBATCH, THREADS>>>(wq, bq, wk, bk, attn);
    dga_gemm<<<NBATCH * 4, THREADS, SMEM_TOTAL>>>(x, attn, out);
}

// round 7
// speedup vs baseline: 1.2910x; 1.0236x over previous
#include <cuda_runtime.h>
#include <cstring>

#define NBATCH 256
#define NN     64
#define DT     4096
#define THREADS 256

__device__ float e_scratch[NBATCH * NN];   // row variances (K1a -> K1b)

__device__ __forceinline__ void fma2(unsigned long long &d,
                                     unsigned long long a,
                                     unsigned long long b) {
    asm("fma.rn.f32x2 %0, %1, %2, %0;" : "+l"(d) : "l"(a), "l"(b));
}
__device__ __forceinline__ unsigned long long dup2(float w) {
    unsigned long long r;
    asm("mov.b64 %0, {%1, %1};" : "=l"(r) : "f"(w));
    return r;
}
__device__ __forceinline__ void cp_async16(void* smem_dst, const void* gsrc) {
    unsigned sa = (unsigned)__cvta_generic_to_shared(smem_dst);
    asm volatile("cp.async.cg.shared.global [%0], [%1], 16;" :: "r"(sa), "l"(gsrc));
}

// ============================================================================
// K1a: row variances (ddof=1). 1024 blocks = (batch, 16-row group).
// Two independent row streams interleaved for 2x MLP.
// ============================================================================
__global__ void __launch_bounds__(THREADS, 4)
dga_var(const float* __restrict__ x)
{
    const int b    = blockIdx.x >> 2;
    const int g    = blockIdx.x & 3;
    const int tid  = threadIdx.x;
    const int warp = tid >> 5;
    const int lane = tid & 31;
    const float* xb = x + (size_t)b * NN * DT;

    const int r0 = g * 16 + warp * 2;
    const float4* rowA = (const float4*)(xb + (size_t)r0 * DT);
    const float4* rowB = (const float4*)(xb + (size_t)(r0 + 1) * DT);
    float sA = 0.f, ssA = 0.f, sB = 0.f, ssB = 0.f;
    #pragma unroll
    for (int k = 0; k < 32; ++k) {
        float4 a = rowA[lane + 32 * k];
        float4 c = rowB[lane + 32 * k];
        sA  += (a.x + a.y) + (a.z + a.w);
        ssA += a.x * a.x + a.y * a.y + a.z * a.z + a.w * a.w;
        sB  += (c.x + c.y) + (c.z + c.w);
        ssB += c.x * c.x + c.y * c.y + c.z * c.z + c.w * c.w;
    }
    #pragma unroll
    for (int m = 16; m; m >>= 1) {
        sA  += __shfl_xor_sync(0xffffffffu, sA,  m);
        ssA += __shfl_xor_sync(0xffffffffu, ssA, m);
        sB  += __shfl_xor_sync(0xffffffffu, sB,  m);
        ssB += __shfl_xor_sync(0xffffffffu, ssB, m);
    }
    if (lane == 0) {
        float meanA = sA * (1.0f / DT);
        float meanB = sB * (1.0f / DT);
        e_scratch[b * NN + r0]     = (ssA - sA * meanA) * (1.0f / (DT - 1));
        e_scratch[b * NN + r0 + 1] = (ssB - sB * meanB) * (1.0f / (DT - 1));
    }
}

// ============================================================================
// K1b: 4 scalar coefs -> masked softmax -> attn_weights. 256 blocks.
// ============================================================================
__global__ void __launch_bounds__(THREADS)
dga_weights(const float* __restrict__ wq, const float* __restrict__ bq,
            const float* __restrict__ wk, const float* __restrict__ bk,
            float* __restrict__ attn)
{
    __shared__ float e_sm[NN];
    __shared__ float coef[4];

    const int b   = blockIdx.x;
    const int tid = threadIdx.x;

    if (tid < NN) e_sm[tid] = e_scratch[b * NN + tid];
    if (tid == 0) {
        float A = 0.f, B = 0.f, C = 0.f, Dc = 0.f;
        #pragma unroll
        for (int h = 0; h < 16; ++h) {
            float q = wq[h], qb = bq[h], k = wk[h], kb = bk[h];
            A += q * k; B += q * kb; C += qb * k; Dc += qb * kb;
        }
        coef[0] = A; coef[1] = B; coef[2] = C; coef[3] = Dc;
    }
    __syncthreads();

    const int i  = tid >> 2;
    const int jg = tid & 3;
    const float ei = e_sm[i];
    const float m1 = 0.25f * (coef[0] * ei + coef[2]);   // SCALE = 0.25
    const float m0 = 0.25f * (coef[1] * ei + coef[3]);
    float sv[16];
    float mx = -3.4e38f;
    #pragma unroll
    for (int t = 0; t < 16; ++t) {
        int j = jg * 16 + t;
        float s = fmaf(m1, e_sm[j], m0);
        if (j == i) s = -1000000000.0f;
        sv[t] = s;
        mx = fmaxf(mx, s);
    }
    #pragma unroll
    for (int m = 1; m < 4; m <<= 1)
        mx = fmaxf(mx, __shfl_xor_sync(0xffffffffu, mx, m));
    float sum = 0.f;
    #pragma unroll
    for (int t = 0; t < 16; ++t) { sv[t] = __expf(sv[t] - mx); sum += sv[t]; }
    #pragma unroll
    for (int m = 1; m < 4; m <<= 1)
        sum += __shfl_xor_sync(0xffffffffu, sum, m);
    float inv = 1.0f / sum;

    float* arow = attn + (((size_t)b * NN) + i) * NN;
    #pragma unroll
    for (int t = 0; t < 16; ++t)
        arow[jg * 16 + t] = sv[t] * inv;
}

// ============================================================================
// K2: out[b,i,t] = x[b,i,t] + sum_j attn[b,i,j] * x[b,j,t]
// 1024 blocks = (batch, quarter = 512 pairs = 8 chunks of 64 pairs).
// Double-buffered cp.async pipeline: stage chunk c+1 while computing chunk c.
// smem: 17 KB weights + 2 x 32 KB vs = 83 KB -> 2 blocks/SM.
// Per thread: 8 rows x 2 pairs. Per k per warp: 1 v-LDS.128 + 2 bcast
// w-LDS.128 + 8 ALU dup -> 16 FFMA2.
// ============================================================================
#define WPAD 68                                     // floats per wT row (272B)
#define CH   64                                     // pairs per chunk
#define SMEM_W_BYTES (NN * WPAD * 4)                // 17408
#define SMEM_VS_BYTES (NN * CH * 8)                 // 32768 per buffer
#define SMEM_TOTAL   (SMEM_W_BYTES + 2 * SMEM_VS_BYTES)   // 82944

__global__ void __launch_bounds__(THREADS, 2)
dga_gemm(const float* __restrict__ x, const float* __restrict__ attn,
         float* __restrict__ out)
{
    extern __shared__ char smem_raw[];
    float  (*wT)[WPAD] = (float (*)[WPAD])smem_raw;              // [j][i]
    float2* vs_base    = (float2*)(smem_raw + SMEM_W_BYTES);     // [2][64][64]

    const int bx   = blockIdx.x;
    const int b    = bx >> 2;
    const int q    = bx & 3;
    const int tid  = threadIdx.x;
    const int warp = tid >> 5;
    const int lane = tid & 31;

    const float* xb = x    + (size_t)b * NN * DT;
    const float* ab = attn + (size_t)b * NN * NN;
    float*       ob = out  + (size_t)b * NN * DT;

    // stage weights transposed (non-dup): attn[i][j] -> wT[j][i]
    #pragma unroll
    for (int t = 0; t < 16; ++t) {
        int idx = tid + 256 * t;          // coalesced gmem read
        int i = idx >> 6, j = idx & 63;
        wT[j][i] = ab[idx];
    }

    const int i0 = warp * 8;              // this warp's 8 output rows
    const int pbase0 = q * 512;

    // ---- stage chunk 0 ----
    {
        float2* vs0 = vs_base;            // buffer 0
        #pragma unroll
        for (int t = 0; t < 8; ++t) {
            int u  = tid + 256 * t;       // 2048 16B units
            int j  = u >> 5;
            int f4 = u & 31;
            cp_async16(&vs0[j * CH + f4 * 2],
                       xb + (size_t)j * DT + 2 * pbase0 + f4 * 4);
        }
        asm volatile("cp.async.commit_group;");
    }

    #pragma unroll 1
    for (int c = 0; c < 8; ++c) {
        const int pbase = pbase0 + c * CH;
        float2* vsc = vs_base + (c & 1) * (NN * CH);

        // stage chunk c+1 into the other buffer (its last use was compute
        // c-1, guarded by the end-of-iteration barrier below)
        if (c + 1 < 8) {
            float2* vsn = vs_base + ((c + 1) & 1) * (NN * CH);
            const float* src = xb + 2 * (pbase0 + (c + 1) * CH);
            #pragma unroll
            for (int t = 0; t < 8; ++t) {
                int u  = tid + 256 * t;
                int j  = u >> 5;
                int f4 = u & 31;
                cp_async16(&vsn[j * CH + f4 * 2],
                           src + (size_t)j * DT + f4 * 4);
            }
            asm volatile("cp.async.commit_group;");
            asm volatile("cp.async.wait_group 1;");   // chunk c arrived
        } else {
            asm volatile("cp.async.wait_group 0;");
        }
        __syncthreads();

        // accumulators init = residual x (folds the "+ x")
        unsigned long long acc[8][2];
        #pragma unroll
        for (int r = 0; r < 8; ++r) {
            ulonglong2 t2 = *(const ulonglong2*)&vsc[(i0 + r) * CH + 2 * lane];
            acc[r][0] = t2.x; acc[r][1] = t2.y;
        }

        #pragma unroll 4
        for (int k = 0; k < NN; ++k) {
            ulonglong2 v = *(const ulonglong2*)&vsc[k * CH + 2 * lane];
            float4 wa = *(const float4*)&wT[k][i0];      // bcast LDS.128
            float4 wb = *(const float4*)&wT[k][i0 + 4];  // bcast LDS.128
            unsigned long long w0 = dup2(wa.x), w1 = dup2(wa.y);
            unsigned long long w2 = dup2(wa.z), w3 = dup2(wa.w);
            unsigned long long w4 = dup2(wb.x), w5 = dup2(wb.y);
            unsigned long long w6 = dup2(wb.z), w7 = dup2(wb.w);
            fma2(acc[0][0], w0, v.x); fma2(acc[0][1], w0, v.y);
            fma2(acc[1][0], w1, v.x); fma2(acc[1][1], w1, v.y);
            fma2(acc[2][0], w2, v.x); fma2(acc[2][1], w2, v.y);
            fma2(acc[3][0], w3, v.x); fma2(acc[3][1], w3, v.y);
            fma2(acc[4][0], w4, v.x); fma2(acc[4][1], w4, v.y);
            fma2(acc[5][0], w5, v.x); fma2(acc[5][1], w5, v.y);
            fma2(acc[6][0], w6, v.x); fma2(acc[6][1], w6, v.y);
            fma2(acc[7][0], w7, v.x); fma2(acc[7][1], w7, v.y);
        }

        // store (coalesced STG.128 per warp)
        #pragma unroll
        for (int r = 0; r < 8; ++r) {
            unsigned long long* orow =
                (unsigned long long*)(ob + (size_t)(i0 + r) * DT) + pbase;
            ulonglong2 t2; t2.x = acc[r][0]; t2.y = acc[r][1];
            *(ulonglong2*)&orow[2 * lane] = t2;
        }
        __syncthreads();   // compute(c) done before next iter stages into vsc
    }
}

extern "C" void kernel_launch(void* const* d_in, const int* in_sizes, int n_in,
                              void* d_out, int out_size) {
    const float* x  = (const float*)d_in[0];
    const float* wq = (const float*)d_in[1];
    const float* bq = (const float*)d_in[2];
    const float* wk = (const float*)d_in[3];
    const float* bk = (const float*)d_in[4];
    float* out  = (float*)d_out;
    float* attn = out + (size_t)NBATCH * NN * DT;   // out tensor first, then attn

    cudaFuncSetAttribute(dga_gemm, cudaFuncAttributeMaxDynamicSharedMemorySize,
                         SMEM_TOTAL);

    dga_var<<<NBATCH * 4, THREADS>>>(x);
    dga_weights<<<NBATCH, THREADS>>>(wq, bq, wk, bk, attn);
    dga_gemm<<<NBATCH * 4, THREADS, SMEM_TOTAL>>>(x, attn, out);
}